// round 1
// baseline (speedup 1.0000x reference)
#include <cuda_runtime.h>
#include <cuda_bf16.h>
#include <math.h>

#define NEGV (-1e10f)

#define KSPAN 1024        // number of spans k
#define KANT 50           // antecedents per span
#define GIDIM 512
#define GIJ 1596
#define HID 1000
#define MROWS (KSPAN*KANT)   // 51200
#define KPAD 1600
#define NPAD 1024
#define NSLOTS 16         // 8 n-tiles * 2 wn warps

// ------------------ device scratch (no runtime allocation) ------------------
__device__ float d_proj[KSPAN*GIDIM];
__device__ float d_ant[KSPAN*KSPAN];
__device__ float d_bs[KSPAN*KANT];
__device__ int   d_bi[KSPAN*KANT];
__device__ __nv_bfloat16 d_A[(size_t)MROWS*KPAD];
__device__ __nv_bfloat16 d_Bt[(size_t)NPAD*KPAD];
__device__ float d_b1p[NPAD];
__device__ float d_w2p[NPAD];
__device__ float d_WfT[(size_t)GIDIM*(2*GIDIM)];   // [512][1024]
__device__ float d_part[(size_t)NSLOTS*MROWS];
__device__ float d_sa[MROWS];
__device__ float d_an[KSPAN*GIDIM];
__device__ float d_gnext[KSPAN*GIDIM];

// ------------------ prep kernels ------------------
__global__ void prep_bt(const float* __restrict__ W1){
    int idx = blockIdx.x*256 + threadIdx.x;
    if (idx >= NPAD*KPAD) return;
    int n = idx / KPAD, k = idx - n*KPAD;
    float v = (n < HID && k < GIJ) ? W1[(size_t)k*HID + n] : 0.f;
    d_Bt[idx] = __float2bfloat16(v);
}

__global__ void prep_vec(const float* __restrict__ b1, const float* __restrict__ W2){
    int idx = blockIdx.x*256 + threadIdx.x;
    if (idx < NPAD){
        d_b1p[idx] = (idx < HID) ? b1[idx] : 0.f;
        d_w2p[idx] = (idx < HID) ? W2[idx] : 0.f;
    }
}

__global__ void prep_wft(const float* __restrict__ Wf){
    int idx = blockIdx.x*256 + threadIdx.x;
    if (idx >= GIDIM*2*GIDIM) return;
    int n = idx / (2*GIDIM), k = idx - n*(2*GIDIM);
    d_WfT[idx] = Wf[(size_t)k*GIDIM + n];
}

// ------------------ generic fp32 GEMM  C = A @ B^T  (64x64 tile) ------------------
// mode 0: proj = g @ coarseW^T            (P0=g, P1=coarseW)     -> d_proj
// mode 1: ant  = proj @ g^T + s_m + s_n + mask  (P0=g, P1=s)     -> d_ant
// mode 2: gate: A=[g|a_n], B=WfT; f=sigmoid(acc+bf); gnext       (P0=g, P1=bf)
__global__ void gemm_f32(int mode, const float* __restrict__ P0,
                         const float* __restrict__ P1, int Kdim){
    __shared__ float As[64][17];
    __shared__ float Bs[64][17];
    int n0 = blockIdx.x*64, m0 = blockIdx.y*64;
    int tid = threadIdx.x;
    int tx = tid & 15, ty = tid >> 4;
    float acc[4][4];
    #pragma unroll
    for (int i=0;i<4;i++)
        #pragma unroll
        for (int j=0;j<4;j++) acc[i][j]=0.f;

    for (int k0 = 0; k0 < Kdim; k0 += 16){
        #pragma unroll
        for (int it=0; it<4; it++){
            int e = tid + it*256;
            int r = e >> 4, kk = e & 15;
            int gk = k0 + kk;
            float av, bv;
            int gm = m0 + r, gn = n0 + r;
            if (mode == 0){
                av = P0[(size_t)gm*GIDIM + gk];
                bv = P1[(size_t)gn*GIDIM + gk];
            } else if (mode == 1){
                av = d_proj[(size_t)gm*GIDIM + gk];
                bv = P0[(size_t)gn*GIDIM + gk];
            } else {
                av = (gk < GIDIM) ? P0[(size_t)gm*GIDIM + gk]
                                  : d_an[(size_t)gm*GIDIM + gk - GIDIM];
                bv = d_WfT[(size_t)gn*(2*GIDIM) + gk];
            }
            As[r][kk] = av;
            Bs[r][kk] = bv;
        }
        __syncthreads();
        #pragma unroll
        for (int kk=0; kk<16; kk++){
            float a4[4], b4[4];
            #pragma unroll
            for (int i=0;i<4;i++) a4[i] = As[ty*4+i][kk];
            #pragma unroll
            for (int j=0;j<4;j++) b4[j] = Bs[tx*4+j][kk];
            #pragma unroll
            for (int i=0;i<4;i++)
                #pragma unroll
                for (int j=0;j<4;j++) acc[i][j] += a4[i]*b4[j];
        }
        __syncthreads();
    }
    #pragma unroll
    for (int i=0;i<4;i++){
        int gm = m0 + ty*4 + i;
        #pragma unroll
        for (int j=0;j<4;j++){
            int gn = n0 + tx*4 + j;
            float v = acc[i][j];
            if (mode == 0){
                d_proj[(size_t)gm*GIDIM + gn] = v;
            } else if (mode == 1){
                v += P1[gm] + P1[gn];
                if (gn >= gm) v += NEGV;
                d_ant[(size_t)gm*KSPAN + gn] = v;
            } else {
                float f = 1.f/(1.f + expf(-(v + P1[gn])));
                float gv = P0[(size_t)gm*GIDIM + gn];
                float av = d_an[(size_t)gm*GIDIM + gn];
                d_gnext[(size_t)gm*GIDIM + gn] = (gm == 0) ? gv : f*gv + (1.f-f)*av;
            }
        }
    }
}

// ------------------ top-K via full bitonic sort of (value desc, idx asc) ------------------
__global__ void topk_kernel(){
    int row = blockIdx.x;
    __shared__ unsigned long long sk[1024];
    for (int j = threadIdx.x; j < 1024; j += 512){
        float v = d_ant[(size_t)row*KSPAN + j];
        unsigned int b = __float_as_uint(v);
        unsigned int asc = (b & 0x80000000u) ? ~b : (b | 0x80000000u);
        sk[j] = (((unsigned long long)(~asc)) << 32) | (unsigned int)j;
    }
    __syncthreads();
    for (int k = 2; k <= 1024; k <<= 1){
        for (int j = k >> 1; j > 0; j >>= 1){
            for (int i = threadIdx.x; i < 1024; i += 512){
                int ixj = i ^ j;
                if (ixj > i){
                    bool up = ((i & k) == 0);
                    unsigned long long a = sk[i], b = sk[ixj];
                    if ((a > b) == up){ sk[i] = b; sk[ixj] = a; }
                }
            }
            __syncthreads();
        }
    }
    if (threadIdx.x < KANT){
        unsigned long long key = sk[threadIdx.x];
        int j = (int)(key & 0xffffffffu);
        d_bi[row*KANT + threadIdx.x] = j;
        d_bs[row*KANT + threadIdx.x] = d_ant[(size_t)row*KSPAN + j];
    }
}

// ------------------ build A matrix [MROWS, KPAD] bf16 ------------------
__global__ void build_A(const float* __restrict__ g_in, int use_gnext,
                        const float* __restrict__ dist_e, const float* __restrict__ genre_e,
                        const float* __restrict__ spk_e,  const int* __restrict__ starts,
                        const int* __restrict__ ends,     const int* __restrict__ gids,
                        const int* __restrict__ sids){
    const float* g = use_gnext ? d_gnext : g_in;
    int warp = threadIdx.x >> 5, lane = threadIdx.x & 31;
    int r = blockIdx.x*8 + warp;
    int i = r / KANT;
    int j = d_bi[r];
    __nv_bfloat16* Arow = d_A + (size_t)r * KPAD;
    const float* gi = g + (size_t)i*GIDIM;
    const float* gj = g + (size_t)j*GIDIM;
    for (int c = lane; c < 256; c += 32){
        float2 a = ((const float2*)gi)[c];
        float2 b = ((const float2*)gj)[c];
        __nv_bfloat162 va, vb, vp;
        va.x = __float2bfloat16(a.x); va.y = __float2bfloat16(a.y);
        vb.x = __float2bfloat16(b.x); vb.y = __float2bfloat16(b.y);
        vp.x = __float2bfloat16(a.x*b.x); vp.y = __float2bfloat16(a.y*b.y);
        ((__nv_bfloat162*)Arow)[c] = va;
        ((__nv_bfloat162*)(Arow + 512))[c] = vb;
        ((__nv_bfloat162*)(Arow + 1024))[c] = vp;
    }
    int d = ends[i] - starts[j];
    int bin = (d>1)+(d>2)+(d>3)+(d>4)+(d>8)+(d>16)+(d>32)+(d>64);
    int gid = gids[i];
    int lab = (sids[i] == sids[j]) ? 1 : 2;
    if (lane < 20){
        Arow[1536+lane] = __float2bfloat16(dist_e[bin*20+lane]);
        Arow[1556+lane] = __float2bfloat16(genre_e[gid*20+lane]);
        Arow[1576+lane] = __float2bfloat16(spk_e[lab*20+lane]);
    }
    if (lane >= 28) Arow[1596 + lane - 28] = __float2bfloat16(0.f);
}

// ------------------ fused MLP GEMM: relu(A@W1+b1)@W2 row-sums ------------------
__device__ __forceinline__ void cpasync16(void* dst, const void* src){
    unsigned int d = (unsigned int)__cvta_generic_to_shared(dst);
    asm volatile("cp.async.cg.shared.global [%0], [%1], 16;\n" :: "r"(d), "l"(src) : "memory");
}

__global__ void __launch_bounds__(256) mlp_gemm(){
    __shared__ unsigned int sA[2][128*20];
    __shared__ unsigned int sB[2][128*20];
    int n0 = blockIdx.x * 128;
    int m0 = blockIdx.y * 128;
    int tid = threadIdx.x, lane = tid & 31, warp = tid >> 5;
    int wm = warp & 3, wn = warp >> 2;
    float acc[2][8][4];
    #pragma unroll
    for (int mi=0;mi<2;mi++)
        #pragma unroll
        for (int ni=0;ni<8;ni++)
            #pragma unroll
            for (int q=0;q<4;q++) acc[mi][ni][q]=0.f;

    auto issue = [&](int buf, int kt){
        int k0 = kt * 32;
        #pragma unroll
        for (int it = 0; it < 2; it++){
            int e = tid + it*256;
            int r = e >> 2, c = e & 3;
            cpasync16(&sA[buf][r*20 + c*4], d_A  + (size_t)(m0+r)*KPAD + k0 + c*8);
            cpasync16(&sB[buf][r*20 + c*4], d_Bt + (size_t)(n0+r)*KPAD + k0 + c*8);
        }
        asm volatile("cp.async.commit_group;\n" ::: "memory");
    };

    issue(0, 0);
    const int KT = KPAD/32;   // 50
    for (int kt = 0; kt < KT; kt++){
        int buf = kt & 1;
        if (kt + 1 < KT){
            issue(buf^1, kt+1);
            asm volatile("cp.async.wait_group 1;\n" ::: "memory");
        } else {
            asm volatile("cp.async.wait_group 0;\n" ::: "memory");
        }
        __syncthreads();
        #pragma unroll
        for (int ks = 0; ks < 2; ks++){
            unsigned int af[2][4], bfr[8][2];
            int arow = wm*32 + (lane>>2);
            int aw = ks*8 + (lane&3);
            #pragma unroll
            for (int mi=0; mi<2; mi++){
                int base = (arow + mi*16)*20;
                af[mi][0] = sA[buf][base + aw];
                af[mi][1] = sA[buf][base + 8*20 + aw];
                af[mi][2] = sA[buf][base + aw + 4];
                af[mi][3] = sA[buf][base + 8*20 + aw + 4];
            }
            int bb = wn*64 + (lane>>2);
            #pragma unroll
            for (int ni=0; ni<8; ni++){
                int base = (bb + ni*8)*20 + ks*8 + (lane&3);
                bfr[ni][0] = sB[buf][base];
                bfr[ni][1] = sB[buf][base + 4];
            }
            #pragma unroll
            for (int mi=0;mi<2;mi++)
                #pragma unroll
                for (int ni=0;ni<8;ni++)
                    asm volatile(
                        "mma.sync.aligned.m16n8k16.row.col.f32.bf16.bf16.f32 "
                        "{%0,%1,%2,%3},{%4,%5,%6,%7},{%8,%9},{%0,%1,%2,%3};\n"
                        : "+f"(acc[mi][ni][0]), "+f"(acc[mi][ni][1]),
                          "+f"(acc[mi][ni][2]), "+f"(acc[mi][ni][3])
                        : "r"(af[mi][0]), "r"(af[mi][1]), "r"(af[mi][2]), "r"(af[mi][3]),
                          "r"(bfr[ni][0]), "r"(bfr[ni][1]));
        }
        __syncthreads();
    }
    // epilogue: relu(acc + b1) * W2, reduce over n within warp, write partial slot
    int slot = blockIdx.x*2 + wn;
    #pragma unroll
    for (int mi=0;mi<2;mi++){
        float rs0 = 0.f, rs1 = 0.f;
        #pragma unroll
        for (int ni=0;ni<8;ni++){
            int n = n0 + wn*64 + ni*8 + (lane&3)*2;
            float b1a = d_b1p[n], b1b = d_b1p[n+1];
            float w2a = d_w2p[n], w2b = d_w2p[n+1];
            rs0 += fmaxf(acc[mi][ni][0]+b1a, 0.f)*w2a + fmaxf(acc[mi][ni][1]+b1b, 0.f)*w2b;
            rs1 += fmaxf(acc[mi][ni][2]+b1a, 0.f)*w2a + fmaxf(acc[mi][ni][3]+b1b, 0.f)*w2b;
        }
        rs0 += __shfl_xor_sync(0xffffffffu, rs0, 1);
        rs0 += __shfl_xor_sync(0xffffffffu, rs0, 2);
        rs1 += __shfl_xor_sync(0xffffffffu, rs1, 1);
        rs1 += __shfl_xor_sync(0xffffffffu, rs1, 2);
        if ((lane & 3) == 0){
            int m = m0 + wm*32 + mi*16 + (lane>>2);
            d_part[(size_t)slot*MROWS + m]     = rs0;
            d_part[(size_t)slot*MROWS + m + 8] = rs1;
        }
    }
}

__global__ void reduce_sa(){
    int m = blockIdx.x*256 + threadIdx.x;
    if (m >= MROWS) return;
    float s = 0.f;
    #pragma unroll
    for (int t=0; t<NSLOTS; t++) s += d_part[(size_t)t*MROWS + m];
    d_sa[m] = s;
}

// ------------------ refinement: softmax + expected antecedent ------------------
__global__ void refine_kernel(const float* __restrict__ g, const float* __restrict__ b2){
    int i = blockIdx.x;
    int nv = min(i, KANT);
    __shared__ float p[KANT+1];
    __shared__ int ji[KANT];
    __shared__ float red[128];
    int tid = threadIdx.x;
    float val;
    if (tid == 0) val = 0.f;
    else if (tid <= KANT){
        int kk = tid - 1;
        val = (kk < nv) ? d_sa[i*KANT+kk] + b2[0] + d_bs[i*KANT+kk] : NEGV;
    } else val = NEGV;
    red[tid] = val; __syncthreads();
    for (int s=64; s>0; s>>=1){ if (tid < s) red[tid] = fmaxf(red[tid], red[tid+s]); __syncthreads(); }
    float mx = red[0]; __syncthreads();
    float e = (tid <= KANT) ? expf(val - mx) : 0.f;
    red[tid] = e; __syncthreads();
    for (int s=64; s>0; s>>=1){ if (tid < s) red[tid] += red[tid+s]; __syncthreads(); }
    float sum = red[0];
    if (tid <= KANT) p[tid] = e / sum;
    if (tid < KANT) ji[tid] = d_bi[i*KANT+tid];
    __syncthreads();
    for (int d = tid; d < GIDIM; d += 128){
        float a = p[0] * g[(size_t)i*GIDIM + d];
        for (int kk = 0; kk < nv; kk++)
            a += p[kk+1] * g[(size_t)ji[kk]*GIDIM + d];
        d_an[(size_t)i*GIDIM + d] = a;
    }
}

// ------------------ final output ------------------
__global__ void final_kernel(const float* __restrict__ b2, float* __restrict__ out){
    int idx = blockIdx.x*256 + threadIdx.x;
    if (idx >= KSPAN*(KANT+1)) return;
    int i = idx / (KANT+1), c = idx - i*(KANT+1);
    float v;
    if (c == 0) v = 0.f;
    else {
        int kk = c - 1;
        if (i == 0) v = (kk == 0) ? 0.f : NEGV;
        else        v = (kk < min(i, KANT)) ? d_sa[i*KANT+kk] + b2[0] + d_bs[i*KANT+kk] : NEGV;
    }
    out[idx] = v;
}

// ------------------ launch ------------------
extern "C" void kernel_launch(void* const* d_in, const int* in_sizes, int n_in,
                              void* d_out, int out_size){
    const float* g_i     = (const float*)d_in[0];
    const float* mention = (const float*)d_in[1];
    const float* dist_e  = (const float*)d_in[2];
    const float* genre_e = (const float*)d_in[3];
    const float* spk_e   = (const float*)d_in[4];
    const float* coarseW = (const float*)d_in[5];
    const float* W1      = (const float*)d_in[6];
    const float* b1      = (const float*)d_in[7];
    const float* W2      = (const float*)d_in[8];
    const float* b2      = (const float*)d_in[9];
    const float* Wf      = (const float*)d_in[10];
    const float* bfv     = (const float*)d_in[11];
    const int* starts    = (const int*)d_in[12];
    const int* ends      = (const int*)d_in[13];
    const int* gids      = (const int*)d_in[14];
    const int* sids      = (const int*)d_in[15];
    float* out = (float*)d_out;

    prep_bt<<<(NPAD*KPAD+255)/256, 256>>>(W1);
    prep_vec<<<(NPAD+255)/256, 256>>>(b1, W2);
    prep_wft<<<(GIDIM*2*GIDIM+255)/256, 256>>>(Wf);

    dim3 g0(GIDIM/64, KSPAN/64);
    gemm_f32<<<g0, 256>>>(0, g_i, coarseW, GIDIM);
    dim3 g1(KSPAN/64, KSPAN/64);
    gemm_f32<<<g1, 256>>>(1, g_i, mention, GIDIM);

    topk_kernel<<<KSPAN, 512>>>();

    for (int it = 0; it < 2; it++){
        build_A<<<MROWS/8, 256>>>(g_i, it, dist_e, genre_e, spk_e, starts, ends, gids, sids);
        dim3 gg(NPAD/128, MROWS/128);
        mlp_gemm<<<gg, 256>>>();
        reduce_sa<<<(MROWS+255)/256, 256>>>();
        if (it == 0){
            refine_kernel<<<KSPAN, 128>>>(g_i, b2);
            dim3 g2(GIDIM/64, KSPAN/64);
            gemm_f32<<<g2, 256>>>(2, g_i, bfv, 2*GIDIM);
        } else {
            final_kernel<<<(KSPAN*(KANT+1)+255)/256, 256>>>(b2, out);
        }
    }
}

// round 2
// speedup vs baseline: 1.0011x; 1.0011x over previous
#include <cuda_runtime.h>
#include <cuda_bf16.h>
#include <math.h>

#define NEGV (-1e10f)

#define KSPAN 1024        // number of spans k
#define KANT 50           // antecedents per span
#define GIDIM 512
#define GIJ 1596
#define HID 1000
#define MROWS (KSPAN*KANT)   // 51200
#define KPAD 1600
#define NPAD 1024
#define NSLOTS 16         // 8 n-tiles * 2 wn warps

// ------------------ device scratch (no runtime allocation) ------------------
__device__ float d_proj[KSPAN*GIDIM];
__device__ float d_ant[KSPAN*KSPAN];
__device__ float d_bs[KSPAN*KANT];
__device__ int   d_bi[KSPAN*KANT];
__device__ __nv_bfloat16 d_A[(size_t)MROWS*KPAD];
__device__ __nv_bfloat16 d_Bt[(size_t)NPAD*KPAD];
__device__ float d_b1p[NPAD];
__device__ float d_w2p[NPAD];
__device__ float d_WfT[(size_t)GIDIM*(2*GIDIM)];   // [512][1024]
__device__ float d_part[(size_t)NSLOTS*MROWS];
__device__ float d_sa[MROWS];
__device__ float d_an[KSPAN*GIDIM];
__device__ float d_gnext[KSPAN*GIDIM];

// ------------------ prep kernels ------------------
__global__ void prep_bt(const float* __restrict__ W1){
    int idx = blockIdx.x*256 + threadIdx.x;
    if (idx >= NPAD*KPAD) return;
    int n = idx / KPAD, k = idx - n*KPAD;
    float v = (n < HID && k < GIJ) ? W1[(size_t)k*HID + n] : 0.f;
    d_Bt[idx] = __float2bfloat16(v);
}

__global__ void prep_vec(const float* __restrict__ b1, const float* __restrict__ W2){
    int idx = blockIdx.x*256 + threadIdx.x;
    if (idx < NPAD){
        d_b1p[idx] = (idx < HID) ? b1[idx] : 0.f;
        d_w2p[idx] = (idx < HID) ? W2[idx] : 0.f;
    }
}

__global__ void prep_wft(const float* __restrict__ Wf){
    int idx = blockIdx.x*256 + threadIdx.x;
    if (idx >= GIDIM*2*GIDIM) return;
    int n = idx / (2*GIDIM), k = idx - n*(2*GIDIM);
    d_WfT[idx] = Wf[(size_t)k*GIDIM + n];
}

// ------------------ generic fp32 GEMM  C = A @ B^T  (64x64 tile) ------------------
// mode 0: proj = g @ coarseW^T            (P0=g, P1=coarseW)     -> d_proj
// mode 1: ant  = proj @ g^T + s_m + s_n + mask  (P0=g, P1=s)     -> d_ant
// mode 2: gate: A=[g|a_n], B=WfT; f=sigmoid(acc+bf); gnext       (P0=g, P1=bf)
__global__ void gemm_f32(int mode, const float* __restrict__ P0,
                         const float* __restrict__ P1, int Kdim){
    __shared__ float As[64][17];
    __shared__ float Bs[64][17];
    int n0 = blockIdx.x*64, m0 = blockIdx.y*64;
    int tid = threadIdx.x;
    int tx = tid & 15, ty = tid >> 4;
    float acc[4][4];
    #pragma unroll
    for (int i=0;i<4;i++)
        #pragma unroll
        for (int j=0;j<4;j++) acc[i][j]=0.f;

    for (int k0 = 0; k0 < Kdim; k0 += 16){
        #pragma unroll
        for (int it=0; it<4; it++){
            int e = tid + it*256;
            int r = e >> 4, kk = e & 15;
            int gk = k0 + kk;
            float av, bv;
            int gm = m0 + r, gn = n0 + r;
            if (mode == 0){
                av = P0[(size_t)gm*GIDIM + gk];
                bv = P1[(size_t)gn*GIDIM + gk];
            } else if (mode == 1){
                av = d_proj[(size_t)gm*GIDIM + gk];
                bv = P0[(size_t)gn*GIDIM + gk];
            } else {
                av = (gk < GIDIM) ? P0[(size_t)gm*GIDIM + gk]
                                  : d_an[(size_t)gm*GIDIM + gk - GIDIM];
                bv = d_WfT[(size_t)gn*(2*GIDIM) + gk];
            }
            As[r][kk] = av;
            Bs[r][kk] = bv;
        }
        __syncthreads();
        #pragma unroll
        for (int kk=0; kk<16; kk++){
            float a4[4], b4[4];
            #pragma unroll
            for (int i=0;i<4;i++) a4[i] = As[ty*4+i][kk];
            #pragma unroll
            for (int j=0;j<4;j++) b4[j] = Bs[tx*4+j][kk];
            #pragma unroll
            for (int i=0;i<4;i++)
                #pragma unroll
                for (int j=0;j<4;j++) acc[i][j] += a4[i]*b4[j];
        }
        __syncthreads();
    }
    #pragma unroll
    for (int i=0;i<4;i++){
        int gm = m0 + ty*4 + i;
        #pragma unroll
        for (int j=0;j<4;j++){
            int gn = n0 + tx*4 + j;
            float v = acc[i][j];
            if (mode == 0){
                d_proj[(size_t)gm*GIDIM + gn] = v;
            } else if (mode == 1){
                v += P1[gm] + P1[gn];
                if (gn >= gm) v += NEGV;
                d_ant[(size_t)gm*KSPAN + gn] = v;
            } else {
                float f = 1.f/(1.f + expf(-(v + P1[gn])));
                float gv = P0[(size_t)gm*GIDIM + gn];
                float av = d_an[(size_t)gm*GIDIM + gn];
                d_gnext[(size_t)gm*GIDIM + gn] = (gm == 0) ? gv : f*gv + (1.f-f)*av;
            }
        }
    }
}

// ------------------ top-K via full bitonic sort of (value desc, idx asc) ------------------
__global__ void topk_kernel(){
    int row = blockIdx.x;
    __shared__ unsigned long long sk[1024];
    for (int j = threadIdx.x; j < 1024; j += 512){
        float v = d_ant[(size_t)row*KSPAN + j];
        unsigned int b = __float_as_uint(v);
        unsigned int asc = (b & 0x80000000u) ? ~b : (b | 0x80000000u);
        sk[j] = (((unsigned long long)(~asc)) << 32) | (unsigned int)j;
    }
    __syncthreads();
    for (int k = 2; k <= 1024; k <<= 1){
        for (int j = k >> 1; j > 0; j >>= 1){
            for (int i = threadIdx.x; i < 1024; i += 512){
                int ixj = i ^ j;
                if (ixj > i){
                    bool up = ((i & k) == 0);
                    unsigned long long a = sk[i], b = sk[ixj];
                    if ((a > b) == up){ sk[i] = b; sk[ixj] = a; }
                }
            }
            __syncthreads();
        }
    }
    if (threadIdx.x < KANT){
        unsigned long long key = sk[threadIdx.x];
        int j = (int)(key & 0xffffffffu);
        d_bi[row*KANT + threadIdx.x] = j;
        d_bs[row*KANT + threadIdx.x] = d_ant[(size_t)row*KSPAN + j];
    }
}

// ------------------ build A matrix [MROWS, KPAD] bf16 ------------------
__global__ void build_A(const float* __restrict__ g_in, int use_gnext,
                        const float* __restrict__ dist_e, const float* __restrict__ genre_e,
                        const float* __restrict__ spk_e,  const int* __restrict__ starts,
                        const int* __restrict__ ends,     const int* __restrict__ gids,
                        const int* __restrict__ sids){
    const float* g = use_gnext ? d_gnext : g_in;
    int warp = threadIdx.x >> 5, lane = threadIdx.x & 31;
    int r = blockIdx.x*8 + warp;
    int i = r / KANT;
    int j = d_bi[r];
    __nv_bfloat16* Arow = d_A + (size_t)r * KPAD;
    const float* gi = g + (size_t)i*GIDIM;
    const float* gj = g + (size_t)j*GIDIM;
    for (int c = lane; c < 256; c += 32){
        float2 a = ((const float2*)gi)[c];
        float2 b = ((const float2*)gj)[c];
        __nv_bfloat162 va, vb, vp;
        va.x = __float2bfloat16(a.x); va.y = __float2bfloat16(a.y);
        vb.x = __float2bfloat16(b.x); vb.y = __float2bfloat16(b.y);
        vp.x = __float2bfloat16(a.x*b.x); vp.y = __float2bfloat16(a.y*b.y);
        ((__nv_bfloat162*)Arow)[c] = va;
        ((__nv_bfloat162*)(Arow + 512))[c] = vb;
        ((__nv_bfloat162*)(Arow + 1024))[c] = vp;
    }
    int d = ends[i] - starts[j];
    int bin = (d>1)+(d>2)+(d>3)+(d>4)+(d>8)+(d>16)+(d>32)+(d>64);
    int gid = gids[i];
    int lab = (sids[i] == sids[j]) ? 1 : 2;
    if (lane < 20){
        Arow[1536+lane] = __float2bfloat16(dist_e[bin*20+lane]);
        Arow[1556+lane] = __float2bfloat16(genre_e[gid*20+lane]);
        Arow[1576+lane] = __float2bfloat16(spk_e[lab*20+lane]);
    }
    if (lane >= 28) Arow[1596 + lane - 28] = __float2bfloat16(0.f);
}

// ------------------ fused MLP GEMM: relu(A@W1+b1)@W2 row-sums ------------------
__device__ __forceinline__ void cpasync16(void* dst, const void* src){
    unsigned int d = (unsigned int)__cvta_generic_to_shared(dst);
    asm volatile("cp.async.cg.shared.global [%0], [%1], 16;\n" :: "r"(d), "l"(src) : "memory");
}

__global__ void __launch_bounds__(256) mlp_gemm(){
    __shared__ unsigned int sA[2][128*20];
    __shared__ unsigned int sB[2][128*20];
    int n0 = blockIdx.x * 128;
    int m0 = blockIdx.y * 128;
    int tid = threadIdx.x, lane = tid & 31, warp = tid >> 5;
    int wm = warp & 3, wn = warp >> 2;
    float acc[2][8][4];
    #pragma unroll
    for (int mi=0;mi<2;mi++)
        #pragma unroll
        for (int ni=0;ni<8;ni++)
            #pragma unroll
            for (int q=0;q<4;q++) acc[mi][ni][q]=0.f;

    auto issue = [&](int buf, int kt){
        int k0 = kt * 32;
        #pragma unroll
        for (int it = 0; it < 2; it++){
            int e = tid + it*256;
            int r = e >> 2, c = e & 3;
            cpasync16(&sA[buf][r*20 + c*4], d_A  + (size_t)(m0+r)*KPAD + k0 + c*8);
            cpasync16(&sB[buf][r*20 + c*4], d_Bt + (size_t)(n0+r)*KPAD + k0 + c*8);
        }
        asm volatile("cp.async.commit_group;\n" ::: "memory");
    };

    issue(0, 0);
    const int KT = KPAD/32;   // 50
    for (int kt = 0; kt < KT; kt++){
        int buf = kt & 1;
        if (kt + 1 < KT){
            issue(buf^1, kt+1);
            asm volatile("cp.async.wait_group 1;\n" ::: "memory");
        } else {
            asm volatile("cp.async.wait_group 0;\n" ::: "memory");
        }
        __syncthreads();
        #pragma unroll
        for (int ks = 0; ks < 2; ks++){
            unsigned int af[2][4], bfr[8][2];
            int arow = wm*32 + (lane>>2);
            int aw = ks*8 + (lane&3);
            #pragma unroll
            for (int mi=0; mi<2; mi++){
                int base = (arow + mi*16)*20;
                af[mi][0] = sA[buf][base + aw];
                af[mi][1] = sA[buf][base + 8*20 + aw];
                af[mi][2] = sA[buf][base + aw + 4];
                af[mi][3] = sA[buf][base + 8*20 + aw + 4];
            }
            int bb = wn*64 + (lane>>2);
            #pragma unroll
            for (int ni=0; ni<8; ni++){
                int base = (bb + ni*8)*20 + ks*8 + (lane&3);
                bfr[ni][0] = sB[buf][base];
                bfr[ni][1] = sB[buf][base + 4];
            }
            #pragma unroll
            for (int mi=0;mi<2;mi++)
                #pragma unroll
                for (int ni=0;ni<8;ni++)
                    asm volatile(
                        "mma.sync.aligned.m16n8k16.row.col.f32.bf16.bf16.f32 "
                        "{%0,%1,%2,%3},{%4,%5,%6,%7},{%8,%9},{%0,%1,%2,%3};\n"
                        : "+f"(acc[mi][ni][0]), "+f"(acc[mi][ni][1]),
                          "+f"(acc[mi][ni][2]), "+f"(acc[mi][ni][3])
                        : "r"(af[mi][0]), "r"(af[mi][1]), "r"(af[mi][2]), "r"(af[mi][3]),
                          "r"(bfr[ni][0]), "r"(bfr[ni][1]));
        }
        __syncthreads();
    }
    // epilogue: relu(acc + b1) * W2, reduce over n within warp, write partial slot
    int slot = blockIdx.x*2 + wn;
    #pragma unroll
    for (int mi=0;mi<2;mi++){
        float rs0 = 0.f, rs1 = 0.f;
        #pragma unroll
        for (int ni=0;ni<8;ni++){
            int n = n0 + wn*64 + ni*8 + (lane&3)*2;
            float b1a = d_b1p[n], b1b = d_b1p[n+1];
            float w2a = d_w2p[n], w2b = d_w2p[n+1];
            rs0 += fmaxf(acc[mi][ni][0]+b1a, 0.f)*w2a + fmaxf(acc[mi][ni][1]+b1b, 0.f)*w2b;
            rs1 += fmaxf(acc[mi][ni][2]+b1a, 0.f)*w2a + fmaxf(acc[mi][ni][3]+b1b, 0.f)*w2b;
        }
        rs0 += __shfl_xor_sync(0xffffffffu, rs0, 1);
        rs0 += __shfl_xor_sync(0xffffffffu, rs0, 2);
        rs1 += __shfl_xor_sync(0xffffffffu, rs1, 1);
        rs1 += __shfl_xor_sync(0xffffffffu, rs1, 2);
        if ((lane & 3) == 0){
            int m = m0 + wm*32 + mi*16 + (lane>>2);
            d_part[(size_t)slot*MROWS + m]     = rs0;
            d_part[(size_t)slot*MROWS + m + 8] = rs1;
        }
    }
}

__global__ void reduce_sa(){
    int m = blockIdx.x*256 + threadIdx.x;
    if (m >= MROWS) return;
    float s = 0.f;
    #pragma unroll
    for (int t=0; t<NSLOTS; t++) s += d_part[(size_t)t*MROWS + m];
    d_sa[m] = s;
}

// ------------------ refinement: softmax + expected antecedent ------------------
__global__ void refine_kernel(const float* __restrict__ g, const float* __restrict__ b2){
    int i = blockIdx.x;
    int nv = min(i, KANT);
    __shared__ float p[KANT+1];
    __shared__ int ji[KANT];
    __shared__ float red[128];
    int tid = threadIdx.x;
    float val;
    if (tid == 0) val = 0.f;
    else if (tid <= KANT){
        int kk = tid - 1;
        val = (kk < nv) ? d_sa[i*KANT+kk] + b2[0] + d_bs[i*KANT+kk] : NEGV;
    } else val = NEGV;
    red[tid] = val; __syncthreads();
    for (int s=64; s>0; s>>=1){ if (tid < s) red[tid] = fmaxf(red[tid], red[tid+s]); __syncthreads(); }
    float mx = red[0]; __syncthreads();
    float e = (tid <= KANT) ? expf(val - mx) : 0.f;
    red[tid] = e; __syncthreads();
    for (int s=64; s>0; s>>=1){ if (tid < s) red[tid] += red[tid+s]; __syncthreads(); }
    float sum = red[0];
    if (tid <= KANT) p[tid] = e / sum;
    if (tid < KANT) ji[tid] = d_bi[i*KANT+tid];
    __syncthreads();
    for (int d = tid; d < GIDIM; d += 128){
        float a = p[0] * g[(size_t)i*GIDIM + d];
        for (int kk = 0; kk < nv; kk++)
            a += p[kk+1] * g[(size_t)ji[kk]*GIDIM + d];
        d_an[(size_t)i*GIDIM + d] = a;
    }
}

// ------------------ final output ------------------
__global__ void final_kernel(const float* __restrict__ b2, float* __restrict__ out){
    int idx = blockIdx.x*256 + threadIdx.x;
    if (idx >= KSPAN*(KANT+1)) return;
    int i = idx / (KANT+1), c = idx - i*(KANT+1);
    float v;
    if (c == 0) v = 0.f;
    else {
        int kk = c - 1;
        if (i == 0) v = (kk == 0) ? 0.f : NEGV;
        else        v = (kk < min(i, KANT)) ? d_sa[i*KANT+kk] + b2[0] + d_bs[i*KANT+kk] : NEGV;
    }
    out[idx] = v;
}

// ------------------ launch ------------------
extern "C" void kernel_launch(void* const* d_in, const int* in_sizes, int n_in,
                              void* d_out, int out_size){
    const float* g_i     = (const float*)d_in[0];
    const float* mention = (const float*)d_in[1];
    const float* dist_e  = (const float*)d_in[2];
    const float* genre_e = (const float*)d_in[3];
    const float* spk_e   = (const float*)d_in[4];
    const float* coarseW = (const float*)d_in[5];
    const float* W1      = (const float*)d_in[6];
    const float* b1      = (const float*)d_in[7];
    const float* W2      = (const float*)d_in[8];
    const float* b2      = (const float*)d_in[9];
    const float* Wf      = (const float*)d_in[10];
    const float* bfv     = (const float*)d_in[11];
    const int* starts    = (const int*)d_in[12];
    const int* ends      = (const int*)d_in[13];
    const int* gids      = (const int*)d_in[14];
    const int* sids      = (const int*)d_in[15];
    float* out = (float*)d_out;

    prep_bt<<<(NPAD*KPAD+255)/256, 256>>>(W1);
    prep_vec<<<(NPAD+255)/256, 256>>>(b1, W2);
    prep_wft<<<(GIDIM*2*GIDIM+255)/256, 256>>>(Wf);

    dim3 g0(GIDIM/64, KSPAN/64);
    gemm_f32<<<g0, 256>>>(0, g_i, coarseW, GIDIM);
    dim3 g1(KSPAN/64, KSPAN/64);
    gemm_f32<<<g1, 256>>>(1, g_i, mention, GIDIM);

    topk_kernel<<<KSPAN, 512>>>();

    for (int it = 0; it < 2; it++){
        build_A<<<MROWS/8, 256>>>(g_i, it, dist_e, genre_e, spk_e, starts, ends, gids, sids);
        dim3 gg(NPAD/128, MROWS/128);
        mlp_gemm<<<gg, 256>>>();
        reduce_sa<<<(MROWS+255)/256, 256>>>();
        if (it == 0){
            refine_kernel<<<KSPAN, 128>>>(g_i, b2);
            dim3 g2(GIDIM/64, KSPAN/64);
            gemm_f32<<<g2, 256>>>(2, g_i, bfv, 2*GIDIM);
        } else {
            final_kernel<<<(KSPAN*(KANT+1)+255)/256, 256>>>(b2, out);
        }
    }
}